// round 11
// baseline (speedup 1.0000x reference)
#include <cuda_runtime.h>
#include <math.h>

#define EPS_F 1.1920928955078125e-07f
#define RED_THREADS 256
#define MAX_C 64
#define CHUNK_L4 32   // float4 per chunk along l => 32*64rows*16B = 32KB/block

// scratch (allocation-free rule): partial sums + final stats
__device__ float g_partials[256 * MAX_C * 2];  // [b][chunk][{sum,sumsq}]
__device__ float g_stats[512];                 // [b][{scale,bias}]

// ---------------------------------------------------------------------------
// Kernel 1: prefix sum & sumsq, UNIFORM 32KB chunks.
// grid = (B, 64): block (b,k) covers l4 in [32k, 32k+32) x ALL 64 rows.
// Every active block moves exactly 32KB -> perfect load balance over ragged zp;
// blocks past zp4 contribute zeros and retire immediately.
// Warp = 32 consecutive l4 at one c (512B coalesced); 8 c-iters/thread (MLP 8).
// ---------------------------------------------------------------------------
__global__ void reduce_kernel(const float* __restrict__ data,
                              const int* __restrict__ zero_pos,
                              int C, int L) {
    int b   = blockIdx.x;
    int k   = blockIdx.y;
    int zp  = zero_pos[b];
    int zp4 = zp >> 2;
    int zrem = zp & 3;
    int l0  = k * CHUNK_L4;
    int tid = threadIdx.x;

    const float*  base = data + (size_t)b * C * L;
    const float4* b4   = (const float4*)base;
    size_t L4 = (size_t)(L >> 2);

    int  l4  = l0 + (tid & 31);
    int  c0  = tid >> 5;                 // 0..7
    bool act = (l4 < zp4);

    float s = 0.0f, sq = 0.0f;
    if (act) {
        float4 v[8];
#pragma unroll
        for (int i = 0; i < 8; i++) {
            int c = c0 + i * 8;
            v[i] = b4[(size_t)c * L4 + l4];      // 8 independent loads in flight
        }
        float s0 = 0.f, q0 = 0.f, s1 = 0.f, q1 = 0.f;
#pragma unroll
        for (int i = 0; i < 8; i += 2) {
            s0 += v[i].x + v[i].y + v[i].z + v[i].w;
            q0 += v[i].x * v[i].x + v[i].y * v[i].y + v[i].z * v[i].z + v[i].w * v[i].w;
            s1 += v[i+1].x + v[i+1].y + v[i+1].z + v[i+1].w;
            q1 += v[i+1].x * v[i+1].x + v[i+1].y * v[i+1].y + v[i+1].z * v[i+1].z + v[i+1].w * v[i+1].w;
        }
        s = s0 + s1;
        sq = q0 + q1;
    }

    // scalar remainder (zp % 4), all 64 rows, handled by the chunk holding zp4
    if (zp4 >= l0 && zp4 < l0 + CHUNK_L4 && (tid & 3) < zrem) {
        int c = tid >> 2;                 // 0..63
        float x = base[(size_t)c * L + (zp4 << 2) + (tid & 3)];
        s  += x;
        sq += x * x;
    }

    // block reduction
    __shared__ float sh_s[RED_THREADS];
    __shared__ float sh_q[RED_THREADS];
    sh_s[tid] = s;
    sh_q[tid] = sq;
    __syncthreads();
    for (int off = RED_THREADS / 2; off >= 32; off >>= 1) {
        if (tid < off) {
            sh_s[tid] += sh_s[tid + off];
            sh_q[tid] += sh_q[tid + off];
        }
        __syncthreads();
    }
    if (tid < 32) {
        float vs = sh_s[tid];
        float vq = sh_q[tid];
        for (int off = 16; off > 0; off >>= 1) {
            vs += __shfl_down_sync(0xFFFFFFFFu, vs, off);
            vq += __shfl_down_sync(0xFFFFFFFFu, vq, off);
        }
        if (tid == 0) {
            int slot = (b * MAX_C + k) * 2;
            g_partials[slot + 0] = vs;   // inactive chunks write 0 (replay-safe)
            g_partials[slot + 1] = vq;
        }
    }
}

// ---------------------------------------------------------------------------
// Kernel 2: fold partials -> scale = 1/(std+eps), bias = -mean*scale.
// ---------------------------------------------------------------------------
__global__ void stats_kernel(const int* __restrict__ zero_pos, int C, int nslots) {
    int b = threadIdx.x;
    float s = 0.0f, sq = 0.0f;
    for (int j = 0; j < nslots; j++) {
        int slot = (b * MAX_C + j) * 2;
        s  += g_partials[slot + 0];
        sq += g_partials[slot + 1];
    }
    float cnt   = (float)C * (float)zero_pos[b];
    float mean  = s / cnt;
    float var   = (sq - cnt * mean * mean) / (cnt - 1.0f);
    float scale = 1.0f / (sqrtf(var) + EPS_F);
    g_stats[2 * b + 0] = scale;
    g_stats[2 * b + 1] = -mean * scale;
}

// ---------------------------------------------------------------------------
// Kernel 3: fused normalize + tail in ONE launch (R10 shape, unchanged).
// ---------------------------------------------------------------------------
__global__ void norm_tail_kernel(const float4* __restrict__ data4,
                                 const int4* __restrict__ idxes4,
                                 const int4* __restrict__ zp4,
                                 float4* __restrict__ out4,
                                 int nb_data, int cl4_shift,
                                 int n4, int nidx4, int ntail4) {
    if (blockIdx.x < nb_data) {
        int base = blockIdx.x * (256 * 4);
        int b    = base >> cl4_shift;           // uniform across block
        float scale = g_stats[2 * b + 0];
        float bias  = g_stats[2 * b + 1];

        int i0 = base + threadIdx.x;
        float4 v0 = data4[i0];
        float4 v1 = data4[i0 + 256];
        float4 v2 = data4[i0 + 512];
        float4 v3 = data4[i0 + 768];

        float4 o0, o1, o2, o3;
        o0.x = fmaf(v0.x, scale, bias); o0.y = fmaf(v0.y, scale, bias);
        o0.z = fmaf(v0.z, scale, bias); o0.w = fmaf(v0.w, scale, bias);
        o1.x = fmaf(v1.x, scale, bias); o1.y = fmaf(v1.y, scale, bias);
        o1.z = fmaf(v1.z, scale, bias); o1.w = fmaf(v1.w, scale, bias);
        o2.x = fmaf(v2.x, scale, bias); o2.y = fmaf(v2.y, scale, bias);
        o2.z = fmaf(v2.z, scale, bias); o2.w = fmaf(v2.w, scale, bias);
        o3.x = fmaf(v3.x, scale, bias); o3.y = fmaf(v3.y, scale, bias);
        o3.z = fmaf(v3.z, scale, bias); o3.w = fmaf(v3.w, scale, bias);

        __stcs(out4 + i0,       o0);
        __stcs(out4 + i0 + 256, o1);
        __stcs(out4 + i0 + 512, o2);
        __stcs(out4 + i0 + 768, o3);
    } else {
        int i = (blockIdx.x - nb_data) * 256 + threadIdx.x;
        if (i < ntail4) {
            int4 t = (i < nidx4) ? __ldcs(idxes4 + i) : __ldcs(zp4 + (i - nidx4));
            float4 o;
            o.x = (float)t.x; o.y = (float)t.y; o.z = (float)t.z; o.w = (float)t.w;
            __stcs(out4 + n4 + i, o);
        }
    }
}

extern "C" void kernel_launch(void* const* d_in, const int* in_sizes, int n_in,
                              void* d_out, int out_size) {
    const float* data     = (const float*)d_in[0];
    const int*   idxes    = (const int*)d_in[1];
    const int*   zero_pos = (const int*)d_in[2];
    float*       out      = (float*)d_out;

    int n_data = in_sizes[0];            // B*C*L = 33554432
    int n_idx  = in_sizes[1];            // B*L   = 524288
    int B      = in_sizes[2];            // 64
    int CL     = n_data / B;             // 524288
    int L      = n_idx / B;              // 8192
    int C      = CL / L;                 // 64

    // 1) reduce: uniform 32KB chunks along l
    int nchunks = (L / 4) / CHUNK_L4;    // 2048/32 = 64
    dim3 g1(B, nchunks);
    reduce_kernel<<<g1, RED_THREADS>>>(data, zero_pos, C, L);

    // 2) stats
    stats_kernel<<<1, B>>>(zero_pos, C, nchunks);

    // 3) fused normalize + tail
    int n4  = n_data / 4;
    int cl4 = CL / 4;
    int cl4_shift = 0;
    while ((1 << cl4_shift) < cl4) cl4_shift++;   // CL/4 power of two

    int nb_data = n4 / (256 * 4);                 // exact tiling (8192 blocks)

    long long extra = (long long)out_size - (long long)n_data;
    int ntail4 = 0, nidx4 = n_idx / 4;
    if (extra > 0) {
        ntail4 = (int)(extra / 4);
        if (ntail4 > nidx4 + B / 4) ntail4 = nidx4 + B / 4;
    }
    int nb_tail = (ntail4 + 255) / 256;

    norm_tail_kernel<<<nb_data + nb_tail, 256>>>((const float4*)data,
                                                 (const int4*)idxes,
                                                 (const int4*)zero_pos,
                                                 (float4*)out,
                                                 nb_data, cl4_shift,
                                                 n4, nidx4, ntail4);
}